// round 3
// baseline (speedup 1.0000x reference)
#include <cuda_runtime.h>
#include <math.h>

// Analytic collapse of the product-state quantum circuit:
//   encoded[b,j] = dot(x[b,:], enc_w[j,:]) + enc_b[j]
//   Theta[j]     = sum_{d<4} theta[d*16 + j]
//   m[b,j]       = cos(Theta[j]) * cos(encoded[b,j])
//   logits[b,c]  = sum_j m[b,j]*cls_w[c, 15-j] + cls_b[c]
//
// Grid = BATCH/2 CTAs (128 <= 148 SMs: one CTA per SM, single wave, no
// cross-CTA L1tex contention). Each warp owns one qubit and computes the
// 512-feature dot for BOTH rows of its CTA's row pair, sharing the enc_w
// loads. Epilogue runs on lanes 0-9 (row 0) and 32-41 (row 1).

#define NQ 16
#define NF 512
#define NC 10

__global__ __launch_bounds__(512, 1)
void hybrid_fcl_fused(const float* __restrict__ x,
                      const float* __restrict__ enc_w,
                      const float* __restrict__ enc_b,
                      const float* __restrict__ theta,
                      const float* __restrict__ cls_w,
                      const float* __restrict__ cls_b,
                      float* __restrict__ out)
{
    const int bp   = blockIdx.x;        // batch row pair: rows 2*bp, 2*bp+1
    const int w    = threadIdx.x >> 5;  // warp id = gate-qubit j (0..15)
    const int lane = threadIdx.x & 31;
    const int tid  = threadIdx.x;

    // ---- prefetch epilogue constants (overlap the x DRAM miss) ----
    // threads 0..9 handle row 0's logits, threads 32..41 handle row 1's.
    const int cls = (w < 2) ? lane : 32;          // class id if < NC
    float4 cw0, cw1, cw2, cw3;
    float  cb = 0.0f;
    if (cls < NC) {
        const float4* cwr = reinterpret_cast<const float4*>(cls_w + cls * NQ);
        cw0 = cwr[0]; cw1 = cwr[1]; cw2 = cwr[2]; cw3 = cwr[3];
        cb  = cls_b[cls];
    }

    // ---- prefetch lane0 constants + hoist cos(Theta) ----
    float cosTh = 0.0f, eb = 0.0f;
    if (lane == 0) {
        eb = enc_b[w];
        float Th = theta[w] + theta[NQ + w] + theta[2 * NQ + w] + theta[3 * NQ + w];
        cosTh = __cosf(Th);
    }

    // ---- dot products for both rows, enc_w loaded once ----
    const float4* __restrict__ xr0 = reinterpret_cast<const float4*>(x + (size_t)(2 * bp)     * NF);
    const float4* __restrict__ xr1 = reinterpret_cast<const float4*>(x + (size_t)(2 * bp + 1) * NF);
    const float4* __restrict__ wr  = reinterpret_cast<const float4*>(enc_w + (size_t)w * NF);

    float4 c0 = wr[lane];       float4 c1 = wr[lane + 32];
    float4 c2 = wr[lane + 64];  float4 c3 = wr[lane + 96];
    float4 a0 = xr0[lane];      float4 a1 = xr0[lane + 32];
    float4 a2 = xr0[lane + 64]; float4 a3 = xr0[lane + 96];
    float4 b0 = xr1[lane];      float4 b1 = xr1[lane + 32];
    float4 b2 = xr1[lane + 64]; float4 b3 = xr1[lane + 96];

    // two independent chains per row (rows independent too)
    float p0 = 0.f, p1 = 0.f, q0 = 0.f, q1 = 0.f;
    p0 = fmaf(a0.x, c0.x, p0); p1 = fmaf(a0.y, c0.y, p1);
    q0 = fmaf(b0.x, c0.x, q0); q1 = fmaf(b0.y, c0.y, q1);
    p0 = fmaf(a0.z, c0.z, p0); p1 = fmaf(a0.w, c0.w, p1);
    q0 = fmaf(b0.z, c0.z, q0); q1 = fmaf(b0.w, c0.w, q1);
    p0 = fmaf(a1.x, c1.x, p0); p1 = fmaf(a1.y, c1.y, p1);
    q0 = fmaf(b1.x, c1.x, q0); q1 = fmaf(b1.y, c1.y, q1);
    p0 = fmaf(a1.z, c1.z, p0); p1 = fmaf(a1.w, c1.w, p1);
    q0 = fmaf(b1.z, c1.z, q0); q1 = fmaf(b1.w, c1.w, q1);
    p0 = fmaf(a2.x, c2.x, p0); p1 = fmaf(a2.y, c2.y, p1);
    q0 = fmaf(b2.x, c2.x, q0); q1 = fmaf(b2.y, c2.y, q1);
    p0 = fmaf(a2.z, c2.z, p0); p1 = fmaf(a2.w, c2.w, p1);
    q0 = fmaf(b2.z, c2.z, q0); q1 = fmaf(b2.w, c2.w, q1);
    p0 = fmaf(a3.x, c3.x, p0); p1 = fmaf(a3.y, c3.y, p1);
    q0 = fmaf(b3.x, c3.x, q0); q1 = fmaf(b3.y, c3.y, q1);
    p0 = fmaf(a3.z, c3.z, p0); p1 = fmaf(a3.w, c3.w, p1);
    q0 = fmaf(b3.z, c3.z, q0); q1 = fmaf(b3.w, c3.w, q1);
    float accA = p0 + p1;
    float accB = q0 + q1;

    // interleaved butterfly reduces (independent, latencies overlap)
#pragma unroll
    for (int off = 16; off; off >>= 1) {
        accA += __shfl_xor_sync(0xFFFFFFFFu, accA, off);
        accB += __shfl_xor_sync(0xFFFFFFFFu, accB, off);
    }

    __shared__ float m[2][NQ];
    if (lane == 0) {
        m[0][w] = cosTh * __cosf(accA + eb);
        m[1][w] = cosTh * __cosf(accB + eb);
    }
    __syncthreads();

    // ---- epilogue: warp0 lanes 0-9 -> row 0, warp1 lanes 0-9 -> row 1 ----
    if (cls < NC && lane < NC) {
        const int r = w;                 // 0 or 1 (only warps 0,1 reach here)
        const float4* ms = reinterpret_cast<const float4*>(m[r]);
        float4 m0 = ms[0], m1 = ms[1], m2 = ms[2], m3 = ms[3];
        float s = cb;
        s = fmaf(m0.x, cw3.w, s); s = fmaf(m0.y, cw3.z, s);
        s = fmaf(m0.z, cw3.y, s); s = fmaf(m0.w, cw3.x, s);
        s = fmaf(m1.x, cw2.w, s); s = fmaf(m1.y, cw2.z, s);
        s = fmaf(m1.z, cw2.y, s); s = fmaf(m1.w, cw2.x, s);
        s = fmaf(m2.x, cw1.w, s); s = fmaf(m2.y, cw1.z, s);
        s = fmaf(m2.z, cw1.y, s); s = fmaf(m2.w, cw1.x, s);
        s = fmaf(m3.x, cw0.w, s); s = fmaf(m3.y, cw0.z, s);
        s = fmaf(m3.z, cw0.y, s); s = fmaf(m3.w, cw0.x, s);
        out[(size_t)(2 * bp + r) * NC + lane] = s;
    }
}

extern "C" void kernel_launch(void* const* d_in, const int* in_sizes, int n_in,
                              void* d_out, int out_size)
{
    const float* x     = (const float*)d_in[0]; // (256, 512)
    const float* enc_w = (const float*)d_in[1]; // (16, 512)
    const float* enc_b = (const float*)d_in[2]; // (16,)
    const float* theta = (const float*)d_in[3]; // (64,)
    const float* cls_w = (const float*)d_in[4]; // (10, 16)
    const float* cls_b = (const float*)d_in[5]; // (10,)
    float* out = (float*)d_out;                 // (256, 10)

    const int batch = in_sizes[0] / NF;         // 256
    hybrid_fcl_fused<<<batch / 2, 512>>>(x, enc_w, enc_b, theta, cls_w, cls_b, out);
}